// round 8
// baseline (speedup 1.0000x reference)
#include <cuda_runtime.h>

#define K_CTX 64
#define D     128
#define DS    200
#define STRIDE 132   // words; 16B-aligned rows; conflict-free f4 access pattern

__device__ float g_AM[K_CTX * D];        // AM = A @ att_mat
__device__ float g_A[K_CTX * D];         // raw A = table[t1_ctx]
__device__ float g_rowp[512 * K_CTX];    // row-sum partials per half-CTA
__device__ float g_colm[256 * K_CTX];    // complete col sums per candidate

__device__ __forceinline__ unsigned long long fma2(unsigned long long a,
                                                   unsigned long long b,
                                                   unsigned long long c) {
    unsigned long long d;
    asm("fma.rn.f32x2 %0, %1, %2, %3;" : "=l"(d) : "l"(a), "l"(b), "l"(c));
    return d;
}
__device__ __forceinline__ float unpack_add(unsigned long long v) {
    unsigned lo, hi;
    asm("mov.b64 {%0,%1}, %2;" : "=r"(lo), "=r"(hi) : "l"(v));
    return __uint_as_float(lo) + __uint_as_float(hi);
}
__device__ __forceinline__ float tanh_fast(float x) {
    x = fminf(fmaxf(x, -15.f), 15.f);
    float e = __expf(2.f * x);
    return __fdividef(e - 1.f, e + 1.f);
}

// ---- prep: AM = table[t1_ctx] @ att ; 1024 thr, 8 d-slices, MLP 8 ----
__global__ __launch_bounds__(1024)
void prep_kernel(const float* __restrict__ table,
                 const float* __restrict__ att,
                 const int* __restrict__ t1_ctx) {
    __shared__ float sA[D];
    __shared__ float partial[8 * D];
    const int k = blockIdx.x;
    const int t = threadIdx.x;
    const int j = t & 127;
    const int s = t >> 7;            // d-slice 0..7, 16 d each

    if (s == 0) sA[j] = table[(size_t)t1_ctx[k] * D + j];
    __syncthreads();

    const int d0 = s * 16;
    float a0 = 0.f, a1 = 0.f, a2 = 0.f, a3 = 0.f;
    float a4 = 0.f, a5 = 0.f, a6 = 0.f, a7 = 0.f;
#pragma unroll
    for (int i = 0; i < 16; i += 8) {
        a0 = fmaf(sA[d0 + i + 0], att[(d0 + i + 0) * D + j], a0);
        a1 = fmaf(sA[d0 + i + 1], att[(d0 + i + 1) * D + j], a1);
        a2 = fmaf(sA[d0 + i + 2], att[(d0 + i + 2) * D + j], a2);
        a3 = fmaf(sA[d0 + i + 3], att[(d0 + i + 3) * D + j], a3);
        a4 = fmaf(sA[d0 + i + 4], att[(d0 + i + 4) * D + j], a4);
        a5 = fmaf(sA[d0 + i + 5], att[(d0 + i + 5) * D + j], a5);
        a6 = fmaf(sA[d0 + i + 6], att[(d0 + i + 6) * D + j], a6);
        a7 = fmaf(sA[d0 + i + 7], att[(d0 + i + 7) * D + j], a7);
    }
    partial[s * D + j] = ((a0 + a1) + (a2 + a3)) + ((a4 + a5) + (a6 + a7));
    __syncthreads();

    if (s == 0) {
        float r = 0.f;
#pragma unroll
        for (int p = 0; p < 8; ++p) r += partial[p * D + j];
        g_AM[k * D + j] = r;
        g_A[k * D + j] = sA[j];
    }
}

// ---- gemm: CTA (c,h): all 64 AM rows x 32 B rows, f32x2 FMA ----
__global__ __launch_bounds__(256, 4)
void gemm_kernel(const float* __restrict__ table,
                 const int* __restrict__ t2_ctx) {
    extern __shared__ float sm[];
    float* sAM     = sm;                      // 64*132
    float* sB      = sAM + K_CTX * STRIDE;    // 32*132
    float* colpart = sB + 32 * STRIDE;        // 8*32

    const int t    = threadIdx.x;
    const int bid  = blockIdx.x;
    const int c    = bid >> 1;
    const int m0   = (bid & 1) << 5;
    const int lane = t & 31;
    const int w    = t >> 5;

    for (int i = t; i < K_CTX * D; i += 256)
        sAM[(i >> 7) * STRIDE + (i & 127)] = g_AM[i];

    {
        const int r = t >> 3, l = t & 7;
        size_t idx = (size_t)t2_ctx[c * K_CTX + m0 + r];
        const float4* src = (const float4*)(table + idx * D);
        float4* dst = (float4*)(sB + r * STRIDE);
#pragma unroll
        for (int q = 0; q < 4; ++q)
            dst[l + 8 * q] = src[l + 8 * q];
    }
    __syncthreads();

    // 64x32x128: 4x2 tiles, rows ty+16p, cols tx+16q, packed f32x2 along d
    const int tx = t & 15, ty = t >> 4;
    unsigned long long acc[4][2];
#pragma unroll
    for (int p = 0; p < 4; ++p) { acc[p][0] = 0ull; acc[p][1] = 0ull; }

    {
        const float* pa = sAM + ty * STRIDE;
        const float* pb = sB  + tx * STRIDE;
#pragma unroll 2
        for (int dd = 0; dd < D; dd += 4) {
            ulonglong2 a0 = *(const ulonglong2*)(pa + dd);
            ulonglong2 a1 = *(const ulonglong2*)(pa + 16 * STRIDE + dd);
            ulonglong2 a2 = *(const ulonglong2*)(pa + 32 * STRIDE + dd);
            ulonglong2 a3 = *(const ulonglong2*)(pa + 48 * STRIDE + dd);
            ulonglong2 b0 = *(const ulonglong2*)(pb + dd);
            ulonglong2 b1 = *(const ulonglong2*)(pb + 16 * STRIDE + dd);
            acc[0][0] = fma2(a0.x, b0.x, acc[0][0]);
            acc[0][1] = fma2(a0.x, b1.x, acc[0][1]);
            acc[1][0] = fma2(a1.x, b0.x, acc[1][0]);
            acc[1][1] = fma2(a1.x, b1.x, acc[1][1]);
            acc[2][0] = fma2(a2.x, b0.x, acc[2][0]);
            acc[2][1] = fma2(a2.x, b1.x, acc[2][1]);
            acc[3][0] = fma2(a3.x, b0.x, acc[3][0]);
            acc[3][1] = fma2(a3.x, b1.x, acc[3][1]);
            acc[0][0] = fma2(a0.y, b0.y, acc[0][0]);
            acc[0][1] = fma2(a0.y, b1.y, acc[0][1]);
            acc[1][0] = fma2(a1.y, b0.y, acc[1][0]);
            acc[1][1] = fma2(a1.y, b1.y, acc[1][1]);
            acc[2][0] = fma2(a2.y, b0.y, acc[2][0]);
            acc[2][1] = fma2(a2.y, b1.y, acc[2][1]);
            acc[3][0] = fma2(a3.y, b0.y, acc[3][0]);
            acc[3][1] = fma2(a3.y, b1.y, acc[3][1]);
        }
    }

    float sv[4][2];
#pragma unroll
    for (int p = 0; p < 4; ++p) {
        sv[p][0] = tanh_fast(unpack_add(acc[p][0]));
        sv[p][1] = tanh_fast(unpack_add(acc[p][1]));
    }

    // row-sum partials (over this half's 32 m)
#pragma unroll
    for (int p = 0; p < 4; ++p) {
        float rs = sv[p][0] + sv[p][1];
        rs += __shfl_xor_sync(0xffffffffu, rs, 1);
        rs += __shfl_xor_sync(0xffffffffu, rs, 2);
        rs += __shfl_xor_sync(0xffffffffu, rs, 4);
        rs += __shfl_xor_sync(0xffffffffu, rs, 8);
        if (tx == 0) g_rowp[bid * K_CTX + ty + 16 * p] = rs;
    }

    // col sums (over all 64 k)
#pragma unroll
    for (int q = 0; q < 2; ++q) {
        float cs = (sv[0][q] + sv[1][q]) + (sv[2][q] + sv[3][q]);
        cs += __shfl_xor_sync(0xffffffffu, cs, 16);
        if (lane < 16) colpart[w * 32 + tx + 16 * q] = cs;
    }
    __syncthreads();
    if (t < 32) {
        float s = 0.f;
#pragma unroll
        for (int ww = 0; ww < 8; ++ww) s += colpart[ww * 32 + t];
        g_colm[c * K_CTX + m0 + t] = s;
    }
}

// ---- score: softmax + attention sums + bilinear + string branch ----
__global__ __launch_bounds__(256)
void score_kernel(const float* __restrict__ table,
                  const float* __restrict__ str_t1,
                  const float* __restrict__ str_t2s,
                  const float* __restrict__ W,
                  const float* __restrict__ b_bi,
                  const int* __restrict__ t2_ctx,
                  float* __restrict__ out) {
    __shared__ float rw[64], cw[64], nA[128], nB[128], red[256], part[32];
    __shared__ int sIdxB[64];

    const int t = threadIdx.x;
    const int c = blockIdx.x;
    const int lane = t & 31;

    float x1 = 0.f, x2 = 0.f;
    if (t < DS) { x1 = str_t1[t]; x2 = str_t2s[c * DS + t]; }

    if (t < 64) {
        rw[t] = (g_rowp[(2 * c) * K_CTX + t] + g_rowp[(2 * c + 1) * K_CTX + t])
                * (1.f / 64.f);
    } else if (t < 128) {
        const int m = t - 64;
        sIdxB[m] = t2_ctx[c * K_CTX + m];
        cw[m] = g_colm[c * K_CTX + m] * (1.f / 64.f);
    }
    __syncthreads();

    if (t < 64) {
        float* vec = (t < 32) ? rw : cw;
        float v0 = vec[lane], v1 = vec[lane + 32];
        float mx = fmaxf(v0, v1);
#pragma unroll
        for (int o = 16; o >= 1; o >>= 1)
            mx = fmaxf(mx, __shfl_xor_sync(0xffffffffu, mx, o));
        float e0 = __expf(v0 - mx), e1 = __expf(v1 - mx);
        float s = e0 + e1;
#pragma unroll
        for (int o = 16; o >= 1; o >>= 1)
            s += __shfl_xor_sync(0xffffffffu, s, o);
        float inv = __fdividef(1.f, s);
        vec[lane] = e0 * inv;
        vec[lane + 32] = e1 * inv;
    }
    __syncthreads();

    if (t < 128) {
        float s0 = 0.f, s1 = 0.f, s2 = 0.f, s3 = 0.f;
#pragma unroll
        for (int k = 0; k < K_CTX; k += 4) {
            s0 = fmaf(rw[k + 0], g_A[(k + 0) * D + t], s0);
            s1 = fmaf(rw[k + 1], g_A[(k + 1) * D + t], s1);
            s2 = fmaf(rw[k + 2], g_A[(k + 2) * D + t], s2);
            s3 = fmaf(rw[k + 3], g_A[(k + 3) * D + t], s3);
        }
        nA[t] = (s0 + s1) + (s2 + s3);
    } else {
        const int dd = t - 128;
        float s0 = 0.f, s1 = 0.f, s2 = 0.f, s3 = 0.f;
        float s4 = 0.f, s5 = 0.f, s6 = 0.f, s7 = 0.f;
#pragma unroll
        for (int k = 0; k < K_CTX; k += 8) {
            s0 = fmaf(cw[k + 0], table[(size_t)sIdxB[k + 0] * D + dd], s0);
            s1 = fmaf(cw[k + 1], table[(size_t)sIdxB[k + 1] * D + dd], s1);
            s2 = fmaf(cw[k + 2], table[(size_t)sIdxB[k + 2] * D + dd], s2);
            s3 = fmaf(cw[k + 3], table[(size_t)sIdxB[k + 3] * D + dd], s3);
            s4 = fmaf(cw[k + 4], table[(size_t)sIdxB[k + 4] * D + dd], s4);
            s5 = fmaf(cw[k + 5], table[(size_t)sIdxB[k + 5] * D + dd], s5);
            s6 = fmaf(cw[k + 6], table[(size_t)sIdxB[k + 6] * D + dd], s6);
            s7 = fmaf(cw[k + 7], table[(size_t)sIdxB[k + 7] * D + dd], s7);
        }
        nB[dd] = ((s0 + s1) + (s2 + s3)) + ((s4 + s5) + (s6 + s7));
    }
    __syncthreads();

    {
        const int col = t & 127, half = t >> 7;
        float s = 0.f;
        const int d0 = half * 64;
#pragma unroll 4
        for (int d = d0; d < d0 + 64; ++d)
            s = fmaf(nA[d], W[d * D + col], s);
        red[t] = s;
    }
    __syncthreads();
    if (t < 128) {
        float v = (red[t] + red[t + 128]) * nB[t];
#pragma unroll
        for (int o = 16; o >= 1; o >>= 1)
            v += __shfl_xor_sync(0xffffffffu, v, o);
        if (lane == 0) part[t >> 5] = v;
    }
    __syncthreads();

    {
        float p11 = x1 * x1, p22 = x2 * x2, p12 = x1 * x2;
#pragma unroll
        for (int o = 16; o >= 1; o >>= 1) {
            p11 += __shfl_xor_sync(0xffffffffu, p11, o);
            p22 += __shfl_xor_sync(0xffffffffu, p22, o);
            p12 += __shfl_xor_sync(0xffffffffu, p12, o);
        }
        const int w = t >> 5;
        if (lane == 0) { part[8 + w] = p11; part[16 + w] = p22; part[24 + w] = p12; }
    }
    __syncthreads();

    if (t == 0) {
        float con = part[0] + part[1] + part[2] + part[3] + b_bi[0];
        float s11 = 0.f, s22 = 0.f, s12 = 0.f;
#pragma unroll
        for (int w = 0; w < 8; ++w) {
            s11 += part[8 + w]; s22 += part[16 + w]; s12 += part[24 + w];
        }
        float n1 = fmaxf(sqrtf(s11), 1e-8f);
        float n2 = fmaxf(sqrtf(s22), 1e-8f);
        out[c] = 0.5f * (s12 / (n1 * n2)) + 0.5f * con;
    }
}

static const int GEMM_SMEM = (K_CTX * STRIDE + 32 * STRIDE + 8 * 32) * 4;

extern "C" void kernel_launch(void* const* d_in, const int* in_sizes, int n_in,
                              void* d_out, int out_size) {
    const float* table   = (const float*)d_in[0];
    const float* str_t1  = (const float*)d_in[1];
    const float* str_t2s = (const float*)d_in[2];
    const float* att_mat = (const float*)d_in[3];
    const float* W_bi    = (const float*)d_in[4];
    const float* b_bi    = (const float*)d_in[5];
    const int*   t1_ctx  = (const int*)d_in[6];
    const int*   t2_ctx  = (const int*)d_in[7];
    float* out = (float*)d_out;

    cudaFuncSetAttribute(gemm_kernel,
                         cudaFuncAttributeMaxDynamicSharedMemorySize, GEMM_SMEM);

    prep_kernel<<<K_CTX, 1024>>>(table, att_mat, t1_ctx);
    gemm_kernel<<<512, 256, GEMM_SMEM>>>(table, t2_ctx);
    score_kernel<<<256, 256>>>(table, str_t1, str_t2s, W_bi, b_bi,
                               t2_ctx, out);
}

// round 9
// speedup vs baseline: 1.0118x; 1.0118x over previous
#include <cuda_runtime.h>

#define K_CTX 64
#define D     128
#define DS    200
#define STRIDE 132   // words; 16B-aligned rows; conflict-free f4 access pattern

__device__ float g_AM[K_CTX * D];        // AM = A @ att_mat
__device__ float g_A[K_CTX * D];         // raw A = table[t1_ctx]

__device__ __forceinline__ unsigned long long fma2(unsigned long long a,
                                                   unsigned long long b,
                                                   unsigned long long c) {
    unsigned long long d;
    asm("fma.rn.f32x2 %0, %1, %2, %3;" : "=l"(d) : "l"(a), "l"(b), "l"(c));
    return d;
}
__device__ __forceinline__ float unpack_add(unsigned long long v) {
    unsigned lo, hi;
    asm("mov.b64 {%0,%1}, %2;" : "=r"(lo), "=r"(hi) : "l"(v));
    return __uint_as_float(lo) + __uint_as_float(hi);
}
__device__ __forceinline__ float tanh_fast(float x) {
    x = fminf(fmaxf(x, -15.f), 15.f);
    float e = __expf(2.f * x);
    return __fdividef(e - 1.f, e + 1.f);
}

// ---- prep: AM = table[t1_ctx] @ att ; flat independent load batch, MLP 32 ----
__global__ __launch_bounds__(1024)
void prep_kernel(const float* __restrict__ table,
                 const float* __restrict__ att,
                 const int* __restrict__ t1_ctx) {
    __shared__ float partial[8 * D];
    const int k = blockIdx.x;
    const int t = threadIdx.x;
    const int j = t & 127;
    const int s = t >> 7;            // d-slice 0..7, 16 d each
    const int d0 = s * 16;

    const size_t idx = (size_t)t1_ctx[k];
    // 16 table elements (one 64B chunk of the row) + 16 att elements: all independent
    float4 a4[4];
    const float4* arow = (const float4*)(table + idx * D);
#pragma unroll
    for (int i = 0; i < 4; ++i) a4[i] = arow[s * 4 + i];
    float w[16];
#pragma unroll
    for (int i = 0; i < 16; ++i) w[i] = att[(d0 + i) * D + j];

    const float* a = (const float*)a4;
    float s0 = 0.f, s1 = 0.f, s2 = 0.f, s3 = 0.f;
#pragma unroll
    for (int i = 0; i < 16; i += 4) {
        s0 = fmaf(a[i + 0], w[i + 0], s0);
        s1 = fmaf(a[i + 1], w[i + 1], s1);
        s2 = fmaf(a[i + 2], w[i + 2], s2);
        s3 = fmaf(a[i + 3], w[i + 3], s3);
    }
    partial[s * D + j] = (s0 + s1) + (s2 + s3);
    __syncthreads();

    if (s == 0) {
        float r = 0.f;
#pragma unroll
        for (int p = 0; p < 8; ++p) r += partial[p * D + j];
        g_AM[k * D + j] = r;
        g_A[k * D + j] = table[idx * D + j];   // L1-hot
    }
}

// ---- fused: per-candidate GEMM + tanh + softmax + attention + bilinear + cosine ----
__global__ __launch_bounds__(512, 2)
void fused_kernel(const float* __restrict__ table,
                  const float* __restrict__ str_t1,
                  const float* __restrict__ str_t2s,
                  const float* __restrict__ W,
                  const float* __restrict__ b_bi,
                  const int* __restrict__ t2_ctx,
                  float* __restrict__ out) {
    extern __shared__ float sm[];
    float* sAM     = sm;                       // 64*132
    float* sB      = sAM + K_CTX * STRIDE;     // 64*132
    float* colpart = sB + K_CTX * STRIDE;      // 16*64
    float* rw      = colpart + 16 * 64;        // 64
    float* cw      = rw + 64;                  // 64
    float* nA      = cw + 64;                  // 128
    float* nB      = nA + 128;                 // 128
    float* red     = nB + 128;                 // 512
    float* part    = red + 512;                // 32

    const int t    = threadIdx.x;
    const int c    = blockIdx.x;
    const int lane = t & 31;
    const int w    = t >> 5;                   // warp 0..15

    // string-branch inputs early
    float x1 = 0.f, x2 = 0.f;
    if (t < DS) { x1 = str_t1[t]; x2 = str_t2s[c * DS + t]; }

    // stage all 64 AM rows (L2-hot broadcast)
    for (int i = t; i < K_CTX * D; i += 512)
        sAM[(i >> 7) * STRIDE + (i & 127)] = g_AM[i];

    // gather 64 B rows: 8 threads/row, 2 float4 each
    {
        const int r = t >> 3, l = t & 7;
        size_t idx = (size_t)t2_ctx[c * K_CTX + r];
        const float4* src = (const float4*)(table + idx * D);
        float4* dst = (float4*)(sB + r * STRIDE);
        dst[l]     = src[l];
        dst[l + 8] = src[l + 8];
        dst[l + 16] = src[l + 16];
        dst[l + 24] = src[l + 24];
    }
    __syncthreads();

    // 64x64x128 GEMM: 2x4 tiles. rows ty+32p (p<2), cols tx+16q (q<4)
    const int tx = t & 15, ty = t >> 4;        // ty 0..31
    unsigned long long acc[2][4];
#pragma unroll
    for (int p = 0; p < 2; ++p)
#pragma unroll
        for (int q = 0; q < 4; ++q) acc[p][q] = 0ull;

    {
        const float* pa = sAM + ty * STRIDE;
        const float* pb = sB  + tx * STRIDE;
#pragma unroll 2
        for (int dd = 0; dd < D; dd += 4) {
            ulonglong2 a0 = *(const ulonglong2*)(pa + dd);
            ulonglong2 a1 = *(const ulonglong2*)(pa + 32 * STRIDE + dd);
            ulonglong2 b0 = *(const ulonglong2*)(pb + dd);
            ulonglong2 b1 = *(const ulonglong2*)(pb + 16 * STRIDE + dd);
            ulonglong2 b2 = *(const ulonglong2*)(pb + 32 * STRIDE + dd);
            ulonglong2 b3 = *(const ulonglong2*)(pb + 48 * STRIDE + dd);
            acc[0][0] = fma2(a0.x, b0.x, acc[0][0]);
            acc[0][1] = fma2(a0.x, b1.x, acc[0][1]);
            acc[0][2] = fma2(a0.x, b2.x, acc[0][2]);
            acc[0][3] = fma2(a0.x, b3.x, acc[0][3]);
            acc[1][0] = fma2(a1.x, b0.x, acc[1][0]);
            acc[1][1] = fma2(a1.x, b1.x, acc[1][1]);
            acc[1][2] = fma2(a1.x, b2.x, acc[1][2]);
            acc[1][3] = fma2(a1.x, b3.x, acc[1][3]);
            acc[0][0] = fma2(a0.y, b0.y, acc[0][0]);
            acc[0][1] = fma2(a0.y, b1.y, acc[0][1]);
            acc[0][2] = fma2(a0.y, b2.y, acc[0][2]);
            acc[0][3] = fma2(a0.y, b3.y, acc[0][3]);
            acc[1][0] = fma2(a1.y, b0.y, acc[1][0]);
            acc[1][1] = fma2(a1.y, b1.y, acc[1][1]);
            acc[1][2] = fma2(a1.y, b2.y, acc[1][2]);
            acc[1][3] = fma2(a1.y, b3.y, acc[1][3]);
        }
    }

    float sv[2][4];
#pragma unroll
    for (int p = 0; p < 2; ++p)
#pragma unroll
        for (int q = 0; q < 4; ++q)
            sv[p][q] = tanh_fast(unpack_add(acc[p][q]));

    // row sums over m (cols): in-reg over q, shuffle over tx bits 1..8
#pragma unroll
    for (int p = 0; p < 2; ++p) {
        float rs = (sv[p][0] + sv[p][1]) + (sv[p][2] + sv[p][3]);
        rs += __shfl_xor_sync(0xffffffffu, rs, 1);
        rs += __shfl_xor_sync(0xffffffffu, rs, 2);
        rs += __shfl_xor_sync(0xffffffffu, rs, 4);
        rs += __shfl_xor_sync(0xffffffffu, rs, 8);
        if (tx == 0) rw[ty + 32 * p] = rs * (1.f / 64.f);
    }

    // col sums over k (rows): in-reg over p, xor16 pairs the two ty in the warp
#pragma unroll
    for (int q = 0; q < 4; ++q) {
        float cs = sv[0][q] + sv[1][q];
        cs += __shfl_xor_sync(0xffffffffu, cs, 16);
        if (lane < 16) colpart[w * 64 + tx + 16 * q] = cs;
    }
    __syncthreads();
    if (t < 64) {
        float s = 0.f;
#pragma unroll
        for (int ww = 0; ww < 16; ++ww) s += colpart[ww * 64 + t];
        cw[t] = s * (1.f / 64.f);
    }
    __syncthreads();

    // dual softmax: warp0 -> rows, warp1 -> cols
    if (t < 64) {
        float* vec = (t < 32) ? rw : cw;
        float v0 = vec[lane], v1 = vec[lane + 32];
        float mx = fmaxf(v0, v1);
#pragma unroll
        for (int o = 16; o >= 1; o >>= 1)
            mx = fmaxf(mx, __shfl_xor_sync(0xffffffffu, mx, o));
        float e0 = __expf(v0 - mx), e1 = __expf(v1 - mx);
        float s = e0 + e1;
#pragma unroll
        for (int o = 16; o >= 1; o >>= 1)
            s += __shfl_xor_sync(0xffffffffu, s, o);
        float inv = __fdividef(1.f, s);
        vec[lane] = e0 * inv;
        vec[lane + 32] = e1 * inv;
    }
    __syncthreads();

    // nA from g_A (L2-hot coalesced), nB from smem sB
    if (t < 128) {
        float s0 = 0.f, s1 = 0.f, s2 = 0.f, s3 = 0.f;
#pragma unroll
        for (int k = 0; k < K_CTX; k += 4) {
            s0 = fmaf(rw[k + 0], g_A[(k + 0) * D + t], s0);
            s1 = fmaf(rw[k + 1], g_A[(k + 1) * D + t], s1);
            s2 = fmaf(rw[k + 2], g_A[(k + 2) * D + t], s2);
            s3 = fmaf(rw[k + 3], g_A[(k + 3) * D + t], s3);
        }
        nA[t] = (s0 + s1) + (s2 + s3);
    } else if (t < 256) {
        const int dd = t - 128;
        float s0 = 0.f, s1 = 0.f, s2 = 0.f, s3 = 0.f;
#pragma unroll
        for (int k = 0; k < K_CTX; k += 4) {
            s0 = fmaf(cw[k + 0], sB[(k + 0) * STRIDE + dd], s0);
            s1 = fmaf(cw[k + 1], sB[(k + 1) * STRIDE + dd], s1);
            s2 = fmaf(cw[k + 2], sB[(k + 2) * STRIDE + dd], s2);
            s3 = fmaf(cw[k + 3], sB[(k + 3) * STRIDE + dd], s3);
        }
        nB[dd] = (s0 + s1) + (s2 + s3);
    }
    __syncthreads();

    // bilinear: split d into 4 quarters across the 512 threads
    {
        const int col = t & 127, quarter = t >> 7;
        const int d0 = quarter * 32;
        float s = 0.f;
#pragma unroll 4
        for (int d = d0; d < d0 + 32; ++d)
            s = fmaf(nA[d], W[d * D + col], s);
        red[t] = s;
    }
    __syncthreads();
    if (t < 128) {
        float v = ((red[t] + red[t + 128]) + (red[t + 256] + red[t + 384])) * nB[t];
#pragma unroll
        for (int o = 16; o >= 1; o >>= 1)
            v += __shfl_xor_sync(0xffffffffu, v, o);
        if (lane == 0) part[w] = v;
    }
    __syncthreads();

    // string cosine branch (7 warps cover DS=200)
    {
        float p11 = x1 * x1, p22 = x2 * x2, p12 = x1 * x2;
#pragma unroll
        for (int o = 16; o >= 1; o >>= 1) {
            p11 += __shfl_xor_sync(0xffffffffu, p11, o);
            p22 += __shfl_xor_sync(0xffffffffu, p22, o);
            p12 += __shfl_xor_sync(0xffffffffu, p12, o);
        }
        if (lane == 0 && w < 8) { part[8 + w] = p11; part[16 + w] = p22; part[24 + w] = p12; }
    }
    __syncthreads();

    if (t == 0) {
        float con = part[0] + part[1] + part[2] + part[3] + b_bi[0];
        float s11 = 0.f, s22 = 0.f, s12 = 0.f;
#pragma unroll
        for (int ww = 0; ww < 7; ++ww) {
            s11 += part[8 + ww]; s22 += part[16 + ww]; s12 += part[24 + ww];
        }
        float n1 = fmaxf(sqrtf(s11), 1e-8f);
        float n2 = fmaxf(sqrtf(s22), 1e-8f);
        out[c] = 0.5f * (s12 / (n1 * n2)) + 0.5f * con;
    }
}

static const int FUSED_SMEM =
    (K_CTX * STRIDE * 2 + 16 * 64 + 64 + 64 + 128 + 128 + 512 + 32) * 4;

extern "C" void kernel_launch(void* const* d_in, const int* in_sizes, int n_in,
                              void* d_out, int out_size) {
    const float* table   = (const float*)d_in[0];
    const float* str_t1  = (const float*)d_in[1];
    const float* str_t2s = (const float*)d_in[2];
    const float* att_mat = (const float*)d_in[3];
    const float* W_bi    = (const float*)d_in[4];
    const float* b_bi    = (const float*)d_in[5];
    const int*   t1_ctx  = (const int*)d_in[6];
    const int*   t2_ctx  = (const int*)d_in[7];
    float* out = (float*)d_out;

    cudaFuncSetAttribute(fused_kernel,
                         cudaFuncAttributeMaxDynamicSharedMemorySize, FUSED_SMEM);

    prep_kernel<<<K_CTX, 1024>>>(table, att_mat, t1_ctx);
    fused_kernel<<<256, 512, FUSED_SMEM>>>(table, str_t1, str_t2s, W_bi, b_bi,
                                           t2_ctx, out);
}

// round 11
// speedup vs baseline: 1.4501x; 1.4332x over previous
#include <cuda_runtime.h>
#include <cuda_bf16.h>
#include <cstdint>

#define K_CTX 64
#define D     128
#define DS    200

__device__ float g_A[K_CTX * D];                  // raw A = table[t1_ctx]
__device__ __nv_bfloat16 g_AMh[K_CTX * D];        // AM row-major bf16 hi
__device__ __nv_bfloat16 g_AMl[K_CTX * D];        // AM row-major bf16 lo

__device__ __forceinline__ uint32_t smem_to_u32(const void* p) {
    uint32_t a;
    asm("{ .reg .u64 t; cvta.to.shared.u64 t, %1; cvt.u32.u64 %0, t; }"
        : "=r"(a) : "l"(p));
    return a;
}
__device__ __forceinline__ void ldm_x4(uint32_t* r, uint32_t addr) {
    asm volatile("ldmatrix.sync.aligned.m8n8.x4.shared.b16 {%0,%1,%2,%3}, [%4];"
        : "=r"(r[0]), "=r"(r[1]), "=r"(r[2]), "=r"(r[3]) : "r"(addr));
}
__device__ __forceinline__ void mma_bf16(float* d, const uint32_t* a,
                                         uint32_t b0, uint32_t b1) {
    asm volatile(
        "mma.sync.aligned.m16n8k16.row.col.f32.bf16.bf16.f32 "
        "{%0,%1,%2,%3}, {%4,%5,%6,%7}, {%8,%9}, {%0,%1,%2,%3};"
        : "+f"(d[0]), "+f"(d[1]), "+f"(d[2]), "+f"(d[3])
        : "r"(a[0]), "r"(a[1]), "r"(a[2]), "r"(a[3]), "r"(b0), "r"(b1));
}
__device__ __forceinline__ float tanh_fast(float x) {
    x = fminf(fmaxf(x, -15.f), 15.f);
    float e = __expf(2.f * x);
    return __fdividef(e - 1.f, e + 1.f);
}

// ---- prep: AM = table[t1_ctx] @ att -> bf16 hi/lo row-major; also g_A ----
__global__ __launch_bounds__(1024)
void prep_kernel(const float* __restrict__ table,
                 const float* __restrict__ att,
                 const int* __restrict__ t1_ctx) {
    __shared__ float partial[8 * D];
    const int k = blockIdx.x;
    const int t = threadIdx.x;
    const int j = t & 127;
    const int s = t >> 7;
    const int d0 = s * 16;

    const size_t idx = (size_t)t1_ctx[k];
    float4 a4[4];
    const float4* arow = (const float4*)(table + idx * D);
#pragma unroll
    for (int i = 0; i < 4; ++i) a4[i] = arow[s * 4 + i];
    float w[16];
#pragma unroll
    for (int i = 0; i < 16; ++i) w[i] = att[(d0 + i) * D + j];

    const float* a = (const float*)a4;
    float s0 = 0.f, s1 = 0.f, s2 = 0.f, s3 = 0.f;
#pragma unroll
    for (int i = 0; i < 16; i += 4) {
        s0 = fmaf(a[i + 0], w[i + 0], s0);
        s1 = fmaf(a[i + 1], w[i + 1], s1);
        s2 = fmaf(a[i + 2], w[i + 2], s2);
        s3 = fmaf(a[i + 3], w[i + 3], s3);
    }
    partial[s * D + j] = (s0 + s1) + (s2 + s3);
    __syncthreads();

    if (s == 0) {
        float r = 0.f;
#pragma unroll
        for (int p = 0; p < 8; ++p) r += partial[p * D + j];
        __nv_bfloat16 hi = __float2bfloat16(r);
        __nv_bfloat16 lo = __float2bfloat16(r - __bfloat162float(hi));
        g_AMh[k * D + j] = hi;
        g_AMl[k * D + j] = lo;
        g_A[k * D + j] = table[idx * D + j];
    }
}

// ---- fused: mma.sync GEMM + tanh + reductions + softmax + bilinear + cosine ----
#define BSTRIDE 68   // words per bf16 image row (272B = 17*16B, ldmatrix conflict-free)
static constexpr int W_AMH = 0;                  // 64*68
static constexpr int W_AML = W_AMH + 64 * BSTRIDE;
static constexpr int W_BH  = W_AML + 64 * BSTRIDE;
static constexpr int W_BL  = W_BH  + 64 * BSTRIDE;
static constexpr int W_SS  = W_BL  + 64 * BSTRIDE;   // 64*65 f32
static constexpr int W_RW  = W_SS + 64 * 65;     // 64
static constexpr int W_CW  = W_RW + 64;          // 64
static constexpr int W_NA  = W_CW + 64;          // 128
static constexpr int W_NB  = W_NA + 128;         // 128
static constexpr int W_RED = W_NB + 128;         // 256
static constexpr int W_PART= W_RED + 256;        // 32
static constexpr int SMEM_WORDS = W_PART + 32;
static constexpr int FUSED_SMEM = SMEM_WORDS * 4;

__global__ __launch_bounds__(256, 2)
void fused_kernel(const float* __restrict__ table,
                  const float* __restrict__ str_t1,
                  const float* __restrict__ str_t2s,
                  const float* __restrict__ W,
                  const float* __restrict__ b_bi,
                  const int* __restrict__ t2_ctx,
                  float* __restrict__ out) {
    extern __shared__ uint32_t smw[];
    float* smf = (float*)smw;

    const int t    = threadIdx.x;
    const int c    = blockIdx.x;
    const int lane = t & 31;
    const int w    = t >> 5;      // 8 warps
    const int wr   = w & 3;       // M-tile (k rows 16wr..)
    const int wc   = w >> 2;      // N-half (m cols 32wc..)
    const uint32_t sbase = smem_to_u32(smw);

    // string-branch inputs early
    float x1 = 0.f, x2 = 0.f;
    if (t < DS) { x1 = str_t1[t]; x2 = str_t2s[c * DS + t]; }

    // stage AM bf16 hi/lo (row-major -> padded rows)
    {
        const uint4* sh = (const uint4*)g_AMh;
        const uint4* sl = (const uint4*)g_AMl;
        uint4* dh = (uint4*)(smw + W_AMH);
        uint4* dl = (uint4*)(smw + W_AML);
#pragma unroll
        for (int i = 0; i < 4; ++i) {
            int idx = t + 256 * i;          // 1024 uint4 per image
            int r = idx >> 4, cc = idx & 15;
            dh[r * 17 + cc] = sh[idx];
            dl[r * 17 + cc] = sl[idx];
        }
    }

    // gather 64 B rows, convert fp32 -> bf16 hi/lo
    {
        const int r = t >> 2, l = t & 3;
        size_t idx = (size_t)t2_ctx[c * K_CTX + r];
        const float4* src = (const float4*)(table + idx * D);
        uint32_t* bh = smw + W_BH + r * BSTRIDE + l * 16;
        uint32_t* bl = smw + W_BL + r * BSTRIDE + l * 16;
#pragma unroll
        for (int i = 0; i < 8; ++i) {
            float4 f = src[l * 8 + i];
            __nv_bfloat162 h01 = __floats2bfloat162_rn(f.x, f.y);
            __nv_bfloat162 h23 = __floats2bfloat162_rn(f.z, f.w);
            __nv_bfloat162 l01 = __floats2bfloat162_rn(
                f.x - __bfloat162float(h01.x), f.y - __bfloat162float(h01.y));
            __nv_bfloat162 l23 = __floats2bfloat162_rn(
                f.z - __bfloat162float(h23.x), f.w - __bfloat162float(h23.y));
            *(uint2*)(bh + 2 * i) = make_uint2(*(uint32_t*)&h01, *(uint32_t*)&h23);
            *(uint2*)(bl + 2 * i) = make_uint2(*(uint32_t*)&l01, *(uint32_t*)&l23);
        }
    }
    __syncthreads();

    // ---- S(64x64) = AM(64x128) @ B(64x128)^T via m16n8k16 bf16, 3-term ----
    float acc[4][4];
#pragma unroll
    for (int i = 0; i < 4; ++i)
#pragma unroll
        for (int j = 0; j < 4; ++j) acc[i][j] = 0.f;

    {
        const uint32_t aoff = (uint32_t)((16 * wr + (lane & 15)) * 272 +
                                         (lane >> 4) * 16);
        const uint32_t aH = sbase + W_AMH * 4 + aoff;
        const uint32_t aL = sbase + W_AML * 4 + aoff;
        const int bn = (lane & 7) + ((lane >> 4) << 3);
        const uint32_t brow = ((lane >> 3) & 1) * 16;

#pragma unroll
        for (int kk = 0; kk < 8; ++kk) {
            uint32_t ah[4], al[4];
            ldm_x4(ah, aH + kk * 32);
            ldm_x4(al, aL + kk * 32);
#pragma unroll
            for (int np = 0; np < 2; ++np) {
                const int n0 = 32 * wc + 16 * np;
                const uint32_t bo = (uint32_t)((n0 + bn) * 272 + kk * 32 + brow);
                uint32_t bh4[4], bl4[4];
                ldm_x4(bh4, sbase + W_BH * 4 + bo);
                ldm_x4(bl4, sbase + W_BL * 4 + bo);
                mma_bf16(acc[2 * np + 0], ah, bh4[0], bh4[1]);
                mma_bf16(acc[2 * np + 0], al, bh4[0], bh4[1]);
                mma_bf16(acc[2 * np + 0], ah, bl4[0], bl4[1]);
                mma_bf16(acc[2 * np + 1], ah, bh4[2], bh4[3]);
                mma_bf16(acc[2 * np + 1], al, bh4[2], bh4[3]);
                mma_bf16(acc[2 * np + 1], ah, bl4[2], bl4[3]);
            }
        }
    }

    // tanh + write S to smem (rows k, cols m; stride 65)
    {
        const int kr = 16 * wr + (lane >> 2);
#pragma unroll
        for (int nt = 0; nt < 4; ++nt) {
            const int m = 32 * wc + 8 * nt + 2 * (lane & 3);
            smf[W_SS + kr * 65 + m]           = tanh_fast(acc[nt][0]);
            smf[W_SS + kr * 65 + m + 1]       = tanh_fast(acc[nt][1]);
            smf[W_SS + (kr + 8) * 65 + m]     = tanh_fast(acc[nt][2]);
            smf[W_SS + (kr + 8) * 65 + m + 1] = tanh_fast(acc[nt][3]);
        }
    }
    __syncthreads();

    // row means (over m) and col means (over k)
    if (t < 64) {
        const float* row = smf + W_SS + t * 65;
        float s = 0.f;
#pragma unroll 8
        for (int m = 0; m < 64; ++m) s += row[m];
        smf[W_RW + t] = s * (1.f / 64.f);
    } else if (t < 128) {
        const int m = t - 64;
        float s = 0.f;
#pragma unroll 8
        for (int k = 0; k < 64; ++k) s += smf[W_SS + k * 65 + m];
        smf[W_CW + m] = s * (1.f / 64.f);
    }
    __syncthreads();

    // dual softmax: warp0 -> rows, warp1 -> cols
    if (t < 64) {
        float* vec = smf + ((t < 32) ? W_RW : W_CW);
        float v0 = vec[lane], v1 = vec[lane + 32];
        float mx = fmaxf(v0, v1);
#pragma unroll
        for (int o = 16; o >= 1; o >>= 1)
            mx = fmaxf(mx, __shfl_xor_sync(0xffffffffu, mx, o));
        float e0 = __expf(v0 - mx), e1 = __expf(v1 - mx);
        float s = e0 + e1;
#pragma unroll
        for (int o = 16; o >= 1; o >>= 1)
            s += __shfl_xor_sync(0xffffffffu, s, o);
        float inv = __fdividef(1.f, s);
        vec[lane] = e0 * inv;
        vec[lane + 32] = e1 * inv;
    }
    __syncthreads();

    // nA from g_A (L2-hot coalesced); nB from bf16 hi/lo smem rows
    if (t < 128) {
        float s0 = 0.f, s1 = 0.f, s2 = 0.f, s3 = 0.f;
        const float* rw = smf + W_RW;
#pragma unroll
        for (int k = 0; k < K_CTX; k += 4) {
            s0 = fmaf(rw[k + 0], g_A[(k + 0) * D + t], s0);
            s1 = fmaf(rw[k + 1], g_A[(k + 1) * D + t], s1);
            s2 = fmaf(rw[k + 2], g_A[(k + 2) * D + t], s2);
            s3 = fmaf(rw[k + 3], g_A[(k + 3) * D + t], s3);
        }
        smf[W_NA + t] = (s0 + s1) + (s2 + s3);
    } else {
        const int dd = t - 128;
        const float* cw = smf + W_CW;
        const uint32_t* bh = smw + W_BH + (dd >> 1);
        const uint32_t* bl = smw + W_BL + (dd >> 1);
        const uint32_t sh = (dd & 1) * 16;
        float a0 = 0.f, a1 = 0.f;
#pragma unroll 8
        for (int m = 0; m < 64; m += 2) {
            uint32_t h0 = bh[m * BSTRIDE], l0 = bl[m * BSTRIDE];
            uint32_t h1 = bh[(m + 1) * BSTRIDE], l1 = bl[(m + 1) * BSTRIDE];
            float v0 = __uint_as_float(((h0 >> sh) & 0xffffu) << 16) +
                       __uint_as_float(((l0 >> sh) & 0xffffu) << 16);
            float v1 = __uint_as_float(((h1 >> sh) & 0xffffu) << 16) +
                       __uint_as_float(((l1 >> sh) & 0xffffu) << 16);
            a0 = fmaf(cw[m], v0, a0);
            a1 = fmaf(cw[m + 1], v1, a1);
        }
        smf[W_NB + dd] = a0 + a1;
    }
    __syncthreads();

    // bilinear: split d across the two thread halves
    {
        const int col = t & 127, half = t >> 7;
        const int d0 = half * 64;
        float s = 0.f;
        const float* nA = smf + W_NA;
#pragma unroll 4
        for (int d = d0; d < d0 + 64; ++d)
            s = fmaf(nA[d], W[d * D + col], s);
        smf[W_RED + t] = s;
    }
    __syncthreads();
    if (t < 128) {
        float v = (smf[W_RED + t] + smf[W_RED + t + 128]) * smf[W_NB + t];
#pragma unroll
        for (int o = 16; o >= 1; o >>= 1)
            v += __shfl_xor_sync(0xffffffffu, v, o);
        if (lane == 0) smf[W_PART + w] = v;
    }

    // string cosine partials (8 warps)
    {
        float p11 = x1 * x1, p22 = x2 * x2, p12 = x1 * x2;
#pragma unroll
        for (int o = 16; o >= 1; o >>= 1) {
            p11 += __shfl_xor_sync(0xffffffffu, p11, o);
            p22 += __shfl_xor_sync(0xffffffffu, p22, o);
            p12 += __shfl_xor_sync(0xffffffffu, p12, o);
        }
        if (lane == 0) {
            smf[W_PART + 8 + w]  = p11;
            smf[W_PART + 16 + w] = p22;
            smf[W_PART + 24 + w] = p12;
        }
    }
    __syncthreads();

    if (t == 0) {
        float con = smf[W_PART + 0] + smf[W_PART + 1] +
                    smf[W_PART + 2] + smf[W_PART + 3] + b_bi[0];
        float s11 = 0.f, s22 = 0.f, s12 = 0.f;
#pragma unroll
        for (int i = 0; i < 8; ++i) {
            s11 += smf[W_PART + 8 + i];
            s22 += smf[W_PART + 16 + i];
            s12 += smf[W_PART + 24 + i];
        }
        float n1 = fmaxf(sqrtf(s11), 1e-8f);
        float n2 = fmaxf(sqrtf(s22), 1e-8f);
        out[c] = 0.5f * (s12 / (n1 * n2)) + 0.5f * con;
    }
}

extern "C" void kernel_launch(void* const* d_in, const int* in_sizes, int n_in,
                              void* d_out, int out_size) {
    const float* table   = (const float*)d_in[0];
    const float* str_t1  = (const float*)d_in[1];
    const float* str_t2s = (const float*)d_in[2];
    const float* att_mat = (const float*)d_in[3];
    const float* W_bi    = (const float*)d_in[4];
    const float* b_bi    = (const float*)d_in[5];
    const int*   t1_ctx  = (const int*)d_in[6];
    const int*   t2_ctx  = (const int*)d_in[7];
    float* out = (float*)d_out;

    cudaFuncSetAttribute(fused_kernel,
                         cudaFuncAttributeMaxDynamicSharedMemorySize, FUSED_SMEM);

    prep_kernel<<<K_CTX, 1024>>>(table, att_mat, t1_ctx);
    fused_kernel<<<256, 256, FUSED_SMEM>>>(table, str_t1, str_t2s, W_bi, b_bi,
                                           t2_ctx, out);
}